// round 9
// baseline (speedup 1.0000x reference)
#include <cuda_runtime.h>
#include <cuda_bf16.h>
#include <cstdint>
#include <math.h>

#define NN 10000
#define NPAD 10112           // 79 * 128
#define NE 320000
#define FIN 512
#define HIDC 256
#define ZC 64
#define NH 8
#define ND0 32
#define ND1 8
#define NEG_SLOPE 0.2f

// ---------------- scratch (static device memory; no allocations) ----------------
__device__ float g_lin0[NN * HIDC];
__device__ float g_gat0[NN * HIDC];
__device__ float g_lin1[NN * ZC];
__device__ float g_lin2[NN * ZC];
__device__ float g_mean[NN * ZC];
__device__ float g_lstd[NN * ZC];
__device__ float g_el[NN * NH];
__device__ float g_er[NN * NH];
__device__ float g_el2[NN * NH];
__device__ float g_er2[NN * NH];
__device__ float g_e[NE * NH];        // per-edge scratch (sorted order)
__device__ int   g_deg[NN];
__device__ int   g_off[NN + 1];
__device__ int   g_cur[NN];
__device__ int   g_ssrc[NE];
__device__ __nv_bfloat16 g_zhi[NPAD * ZC];
__device__ __nv_bfloat16 g_zlo[NPAD * ZC];

// Feature gate: tcgen05 only exists on the 'a' targets.
#if defined(__CUDA_ARCH_FEAT_SM103_ALL) || defined(__CUDA_ARCH_FEAT_SM100_ALL) || defined(__CUDA_ARCH_FEAT_SM101_ALL)
#define HAS_TCGEN05 1
#else
#define HAS_TCGEN05 0
#endif

// ---------------- PTX helpers ----------------
__device__ __forceinline__ uint32_t smem_u32(const void* p) {
    uint32_t a;
    asm("{ .reg .u64 t; cvta.to.shared.u64 t, %1; cvt.u32.u64 %0, t; }" : "=r"(a) : "l"(p));
    return a;
}
__device__ __forceinline__ uint32_t elect1() {
    uint32_t r;
    asm volatile("{ .reg .pred p; elect.sync _|p, 0xFFFFFFFF; selp.b32 %0,1,0,p; }" : "=r"(r));
    return r;
}
#define MBAR_INIT(mbar, cnt) \
    asm volatile("mbarrier.init.shared.b64 [%0], %1;" :: "r"((uint32_t)(mbar)), "r"((uint32_t)(cnt)) : "memory")
#define MBAR_INVAL(mbar) \
    asm volatile("mbarrier.inval.shared.b64 [%0];" :: "r"((uint32_t)(mbar)) : "memory")
#define MBAR_WAIT(mbar, parity) do {                                           \
    uint32_t _m = (uint32_t)(mbar), _p = (uint32_t)(parity), _d;               \
    asm volatile("{ .reg .pred p; mbarrier.try_wait.parity.acquire.cta.shared::cta.b64 p, [%1], %2; selp.b32 %0,1,0,p; }" \
                 : "=r"(_d) : "r"(_m), "r"(_p) : "memory");                    \
    if (!_d) {                                                                 \
        asm volatile("{ .reg .pred P1; WL%=: mbarrier.try_wait.parity.acquire.cta.shared::cta.b64 P1, [%0], %1, 0x989680; @P1 bra.uni WD%=; bra.uni WL%=; WD%=: }" \
                     :: "r"(_m), "r"(_p) : "memory");                          \
    }                                                                          \
} while (0)
#define FENCE_PROXY_ASYNC() asm volatile("fence.proxy.async.shared::cta;" ::: "memory")

#if HAS_TCGEN05
#define TC_ALLOC(saddr, n) \
    asm volatile("tcgen05.alloc.cta_group::1.sync.aligned.shared::cta.b32 [%0], %1;" \
                 :: "r"((uint32_t)(saddr)), "r"((uint32_t)(n)) : "memory")
#define TC_RELINQ() \
    asm volatile("tcgen05.relinquish_alloc_permit.cta_group::1.sync.aligned;")
#define TC_DEALLOC(tmem, n) \
    asm volatile("tcgen05.dealloc.cta_group::1.sync.aligned.b32 %0, %1;" :: "r"(tmem), "r"((uint32_t)(n)))
#define TC_COMMIT(mbar) \
    asm volatile("tcgen05.commit.cta_group::1.mbarrier::arrive::one.shared::cluster.b64 [%0];" \
                 :: "r"((uint32_t)(mbar)) : "memory")
#define TC_FENCE_AFTER() asm volatile("tcgen05.fence::after_thread_sync;" ::: "memory")
#define TC_FENCE_BEFORE() asm volatile("tcgen05.fence::before_thread_sync;" ::: "memory")
#define TC_WAIT_LD() asm volatile("tcgen05.wait::ld.sync.aligned;" ::: "memory")
#define TC_LD_X32(r, tmem_addr) \
    asm volatile( \
        "tcgen05.ld.sync.aligned.32x32b.x32.b32 " \
        "{%0, %1, %2, %3, %4, %5, %6, %7, " \
        " %8, %9, %10, %11, %12, %13, %14, %15, " \
        " %16, %17, %18, %19, %20, %21, %22, %23, " \
        " %24, %25, %26, %27, %28, %29, %30, %31}, [%32];" \
        : "=r"((r)[0]),  "=r"((r)[1]),  "=r"((r)[2]),  "=r"((r)[3]), \
          "=r"((r)[4]),  "=r"((r)[5]),  "=r"((r)[6]),  "=r"((r)[7]), \
          "=r"((r)[8]),  "=r"((r)[9]),  "=r"((r)[10]), "=r"((r)[11]), \
          "=r"((r)[12]), "=r"((r)[13]), "=r"((r)[14]), "=r"((r)[15]), \
          "=r"((r)[16]), "=r"((r)[17]), "=r"((r)[18]), "=r"((r)[19]), \
          "=r"((r)[20]), "=r"((r)[21]), "=r"((r)[22]), "=r"((r)[23]), \
          "=r"((r)[24]), "=r"((r)[25]), "=r"((r)[26]), "=r"((r)[27]), \
          "=r"((r)[28]), "=r"((r)[29]), "=r"((r)[30]), "=r"((r)[31]) \
        : "r"(tmem_addr))

__device__ __forceinline__ void mma_f16_ss(uint32_t d, uint64_t a, uint64_t b,
                                           uint32_t idesc, bool accum) {
    uint32_t en = accum ? 1u : 0u;
    asm volatile(
        "{\n\t"
        ".reg .pred p;\n\t"
        "setp.ne.u32 p, %5, 0;\n\t"
        "tcgen05.mma.cta_group::1.kind::f16 [%0], %1, %2, %3, {%4, %4, %4, %4}, p;\n\t"
        "}"
        :: "r"(d), "l"(a), "l"(b), "r"(idesc), "r"(0u), "r"(en)
        : "memory");
}
#endif  // HAS_TCGEN05

// SW128 SMEM descriptor (version=1, SBO=64, LBO=1)
__device__ __forceinline__ uint64_t mk_desc(uint32_t saddr) {
    const uint64_t BASE =
        (uint64_t(2) << 61) | (uint64_t(1) << 46) | (uint64_t(64) << 32) | (uint64_t(1) << 16);
    return BASE | ((uint64_t)(saddr >> 4) & 0x3FFF);
}
__device__ __forceinline__ uint32_t swz128(uint32_t off) {
    return off ^ ((off >> 3) & 0x70);
}

// ---------------- counting sort of edges by dst ----------------
__global__ void k_zero_deg() {
    int i = blockIdx.x * blockDim.x + threadIdx.x;
    if (i < NN) g_deg[i] = 0;
}

__global__ void k_hist(const int* __restrict__ dst) {
    int i = blockIdx.x * blockDim.x + threadIdx.x;
    if (i < NE) atomicAdd(&g_deg[dst[i]], 1);
}

__global__ void k_scan() {
    const int CH = 10;
    __shared__ int sh[1024];
    int t = threadIdx.x;
    int base = t * CH;
    int vals[CH];
    int loc = 0;
#pragma unroll
    for (int i = 0; i < CH; i++) {
        int idx = base + i;
        vals[i] = (idx < NN) ? g_deg[idx] : 0;
        loc += vals[i];
    }
    sh[t] = loc;
    __syncthreads();
    for (int off = 1; off < 1024; off <<= 1) {
        int v = (t >= off) ? sh[t - off] : 0;
        __syncthreads();
        sh[t] += v;
        __syncthreads();
    }
    int run = sh[t] - loc;
#pragma unroll
    for (int i = 0; i < CH; i++) {
        int idx = base + i;
        if (idx < NN) {
            g_off[idx] = run;
            g_cur[idx] = run;
            run += vals[i];
        }
    }
    if (t == 0) g_off[NN] = NE;
}

__global__ void k_scatter(const int* __restrict__ src, const int* __restrict__ dst) {
    int e = blockIdx.x * blockDim.x + threadIdx.x;
    if (e < NE) {
        int d = dst[e];
        int pos = atomicAdd(&g_cur[d], 1);
        g_ssrc[pos] = src[e];
    }
}

// ---------------- fp32 tiled GEMM ----------------
__global__ __launch_bounds__(256) void k_sgemm(const float* __restrict__ A,
                                               const float* __restrict__ B,
                                               float* __restrict__ C,
                                               int M, int K, int Nn) {
    __shared__ float As[64 * 32];
    __shared__ float Bs[32 * 64];
    int tid = threadIdx.x;
    int tx = tid & 15, ty = tid >> 4;
    int rowBase = blockIdx.y * 64;
    int colBase = blockIdx.x * 64;
    float acc[4][4] = {};

    for (int kb = 0; kb < K; kb += 32) {
        {
            int r = tid >> 3;
            int c = (tid & 7) << 2;
#pragma unroll
            for (int p = 0; p < 2; p++) {
                int rr = r + p * 32;
                int grow = rowBase + rr;
                float4 v = make_float4(0.f, 0.f, 0.f, 0.f);
                if (grow < M) v = *(const float4*)(A + (size_t)grow * K + kb + c);
                *(float4*)(As + rr * 32 + c) = v;
            }
            int r2 = tid >> 4;
            int c2 = (tid & 15) << 2;
#pragma unroll
            for (int p = 0; p < 2; p++) {
                int rr = r2 + p * 16;
                float4 v = *(const float4*)(B + (size_t)(kb + rr) * Nn + colBase + c2);
                *(float4*)(Bs + rr * 64 + c2) = v;
            }
        }
        __syncthreads();
#pragma unroll
        for (int kk = 0; kk < 32; kk++) {
            float4 b0 = *(const float4*)(Bs + kk * 64 + tx * 4);
            float a0 = As[(ty * 4 + 0) * 32 + kk];
            float a1 = As[(ty * 4 + 1) * 32 + kk];
            float a2 = As[(ty * 4 + 2) * 32 + kk];
            float a3 = As[(ty * 4 + 3) * 32 + kk];
            acc[0][0] += a0 * b0.x; acc[0][1] += a0 * b0.y; acc[0][2] += a0 * b0.z; acc[0][3] += a0 * b0.w;
            acc[1][0] += a1 * b0.x; acc[1][1] += a1 * b0.y; acc[1][2] += a1 * b0.z; acc[1][3] += a1 * b0.w;
            acc[2][0] += a2 * b0.x; acc[2][1] += a2 * b0.y; acc[2][2] += a2 * b0.z; acc[2][3] += a2 * b0.w;
            acc[3][0] += a3 * b0.x; acc[3][1] += a3 * b0.y; acc[3][2] += a3 * b0.z; acc[3][3] += a3 * b0.w;
        }
        __syncthreads();
    }
#pragma unroll
    for (int i = 0; i < 4; i++) {
        int grow = rowBase + ty * 4 + i;
        if (grow < M) {
            *(float4*)(C + (size_t)grow * Nn + colBase + tx * 4) =
                make_float4(acc[i][0], acc[i][1], acc[i][2], acc[i][3]);
        }
    }
}

// ---------------- el/er ----------------
template <int D>
__global__ void k_elr(const float* __restrict__ lin,
                      const float* __restrict__ al,
                      const float* __restrict__ ar,
                      float* __restrict__ elo, float* __restrict__ ero) {
    int i = blockIdx.x * blockDim.x + threadIdx.x;
    if (i >= NN * NH) return;
    int n = i / NH, h = i % NH;
    float el = 0.f, er = 0.f;
#pragma unroll
    for (int d = 0; d < D; d++) {
        float v = lin[n * (NH * D) + h * D + d];
        el += v * al[h * D + d];
        er += v * ar[h * D + d];
    }
    elo[i] = el;
    ero[i] = er;
}

// ---------------- fused per-node GAT ----------------
template <int D, bool RELU>
__global__ void k_gat_fused(const float* __restrict__ lin,
                            const float* __restrict__ elp,
                            const float* __restrict__ erp,
                            const float* __restrict__ bias,
                            float* __restrict__ out) {
    const int C = NH * D;
    int n = blockIdx.x;
    int tid = threadIdx.x;
    int beg = g_off[n], end = g_off[n + 1];
    __shared__ int   s_m[NH];
    __shared__ float s_sum[NH];
    __shared__ int   s_src[32];
    __shared__ float s_ex[32 * NH];
    if (tid < NH) { s_m[tid] = __float_as_int(-INFINITY); s_sum[tid] = 0.f; }
    __syncthreads();

    {
        int h = tid & 7;
        float ern = erp[n * NH + h];
        for (int j0 = beg + (tid >> 3); j0 < end; j0 += C / NH) {
            int s = g_ssrc[j0];
            float v = elp[s * NH + h] + ern;
            v = (v > 0.f) ? v : NEG_SLOPE * v;
            g_e[(size_t)j0 * NH + h] = v;
            if (v >= 0.f)
                atomicMax(&s_m[h], __float_as_int(v));
            else
                atomicMin((unsigned int*)&s_m[h], (unsigned int)__float_as_int(v));
        }
    }
    __syncthreads();

    float acc = 0.f;
    int hA = tid / D;
    for (int base = beg; base < end; base += 32) {
        int cnt = min(32, end - base);
        __syncthreads();
        if (tid < cnt) s_src[tid] = g_ssrc[base + tid];
        for (int i = tid; i < cnt * NH; i += C) {
            float ex = __expf(g_e[(size_t)base * NH + i] - __int_as_float(s_m[i & 7]));
            s_ex[i] = ex;
            atomicAdd(&s_sum[i & 7], ex);
        }
        __syncthreads();
        for (int jj = 0; jj < cnt; jj++)
            acc += lin[(size_t)s_src[jj] * C + tid] * s_ex[jj * NH + hA];
    }
    float v = (end > beg) ? acc / s_sum[hA] : 0.f;
    v += bias[tid];
    if (RELU) v = fmaxf(v, 0.f);
    out[(size_t)n * C + tid] = v;
}

// ---------------- z = mean + noise * exp(log_std), then bf16 hi/lo split ----------------
__global__ void k_z(const float* __restrict__ noise, float* __restrict__ zout) {
    int i = blockIdx.x * blockDim.x + threadIdx.x;
    if (i < NN * ZC) zout[i] = g_mean[i] + noise[i] * expf(g_lstd[i]);
}

__global__ void k_split(const float* __restrict__ z) {
    int i = blockIdx.x * blockDim.x + threadIdx.x;
    if (i >= NPAD * ZC) return;
    if (i < NN * ZC) {
        float v = z[i];
        __nv_bfloat16 h = __float2bfloat16(v);
        g_zhi[i] = h;
        g_zlo[i] = __float2bfloat16(v - __bfloat162float(h));
    } else {
        g_zhi[i] = __float2bfloat16(0.f);
        g_zlo[i] = __float2bfloat16(0.f);
    }
}

// ---------------- adj = sigmoid(z @ z^T) via tcgen05, serial multi-tile ----------------
// Grid (CCH, 79). Each CTA: one 128-row panel, ~TPC column tiles, strictly serial
// per tile (identical ordering to the proven single-tile kernel), but TMEM alloc
// and A-tile loads hoisted out of the loop. 65KB smem -> 2 CTAs/SM for overlap.
#define TC_IDESC 0x8200490u
#define CCH 8
#define TPC 10
#define T3_AH 1024
#define T3_AL (1024 + 16384)
#define T3_BH (1024 + 2 * 16384)
#define T3_BL (1024 + 3 * 16384)
#define TC3_SMEM (1024 + 4 * 16384)

#if HAS_TCGEN05
__device__ __forceinline__ void adj_epilogue(uint32_t acc, int r, int col0,
                                             float* __restrict__ adj) {
#pragma unroll
    for (int ch = 0; ch < 4; ch++) {
        uint32_t dr[32];
        TC_LD_X32(dr, acc + ch * 32);
        TC_WAIT_LD();
        if (r < NN) {
            int cbase = col0 + ch * 32;
            float v[32];
#pragma unroll
            for (int j = 0; j < 32; j++)
                v[j] = 1.f / (1.f + __expf(-__uint_as_float(dr[j])));
            float* orow = adj + (size_t)r * NN + cbase;
            if (cbase + 31 < NN) {
#pragma unroll
                for (int q = 0; q < 8; q++)
                    *(float4*)(orow + q * 4) =
                        make_float4(v[q * 4], v[q * 4 + 1], v[q * 4 + 2], v[q * 4 + 3]);
            } else {
#pragma unroll
                for (int j = 0; j < 32; j++)
                    if (cbase + j < NN) orow[j] = v[j];
            }
        }
    }
}
#endif

__global__ __launch_bounds__(128)
void k_adj_tc3(float* __restrict__ adj) {
#if HAS_TCGEN05
    extern __shared__ char smem[];
    uint32_t sb = smem_u32(smem);
    int tid = threadIdx.x, wid = tid >> 5, lid = tid & 31;
    int row0 = blockIdx.y * 128;
    int cbeg = blockIdx.x * TPC;
    int cend = min(cbeg + TPC, NPAD / 128);

    if (wid == 0) {
        TC_ALLOC(sb + 0, 128);
        TC_RELINQ();
    }
    if (tid == 0) MBAR_INIT(sb + 8, 1);

    // load A tiles once (Ah, Al): 128 rows x 128B, SW128
#pragma unroll
    for (int it = 0; it < 8; it++) {
        int idx = it * 128 + tid;
        int r = idx >> 3;
        int c = idx & 7;
        uint32_t sw = swz128((uint32_t)(r * 128 + c * 16));
        *(uint4*)(smem + T3_AH + sw) = *((const uint4*)(g_zhi + (size_t)(row0 + r) * ZC) + c);
        *(uint4*)(smem + T3_AL + sw) = *((const uint4*)(g_zlo + (size_t)(row0 + r) * ZC) + c);
    }
    __syncthreads();

    uint32_t tmem;
    asm volatile("ld.shared.b32 %0, [%1];" : "=r"(tmem) : "r"(sb + 0));
    uint64_t dAh = mk_desc(sb + T3_AH);
    uint64_t dAl = mk_desc(sb + T3_AL);
    uint64_t dBh = mk_desc(sb + T3_BH);
    uint64_t dBl = mk_desc(sb + T3_BL);

    int r = row0 + wid * 32 + lid;
    int ph = 0;

    for (int ct = cbeg; ct < cend; ct++) {
        int col0 = ct * 128;

        // load B tiles (Bh, Bl)
#pragma unroll
        for (int it = 0; it < 8; it++) {
            int idx = it * 128 + tid;
            int rr = idx >> 3;
            int c = idx & 7;
            uint32_t sw = swz128((uint32_t)(rr * 128 + c * 16));
            *(uint4*)(smem + T3_BH + sw) =
                *((const uint4*)(g_zhi + (size_t)(col0 + rr) * ZC) + c);
            *(uint4*)(smem + T3_BL + sw) =
                *((const uint4*)(g_zlo + (size_t)(col0 + rr) * ZC) + c);
        }
        FENCE_PROXY_ASYNC();
        __syncthreads();

        if (wid == 0 && elect1()) {
            bool first = true;
#pragma unroll
            for (int p = 0; p < 3; p++) {
                uint64_t da = (p == 2) ? dAl : dAh;
                uint64_t db = (p == 1) ? dBl : dBh;
#pragma unroll
                for (int k = 0; k < 4; k++) {
                    mma_f16_ss(tmem, da + k * 2, db + k * 2, TC_IDESC, !first);
                    first = false;
                }
            }
            TC_COMMIT(sb + 8);
        }

        MBAR_WAIT(sb + 8, ph & 1);
        ph++;
        TC_FENCE_AFTER();
        adj_epilogue(tmem, r, col0, adj);
        __syncthreads();
    }

    TC_FENCE_BEFORE();
    __syncthreads();
    if (tid == 0) MBAR_INVAL(sb + 8);
    __syncthreads();
    if (wid == 0) TC_DEALLOC(tmem, 128);
#endif  // HAS_TCGEN05
}

// ---------------- launcher ----------------
extern "C" void kernel_launch(void* const* d_in, const int* in_sizes, int n_in,
                              void* d_out, int out_size) {
    const float* features = (const float*)d_in[0];
    const int*   src      = (const int*)d_in[1];
    const int*   dst      = (const int*)d_in[2];
    const float* noise    = (const float*)d_in[3];
    const float* W0  = (const float*)d_in[4];
    const float* al0 = (const float*)d_in[5];
    const float* ar0 = (const float*)d_in[6];
    const float* b0  = (const float*)d_in[7];
    const float* W1  = (const float*)d_in[8];
    const float* al1 = (const float*)d_in[9];
    const float* ar1 = (const float*)d_in[10];
    const float* b1  = (const float*)d_in[11];
    const float* W2  = (const float*)d_in[12];
    const float* al2 = (const float*)d_in[13];
    const float* ar2 = (const float*)d_in[14];
    const float* b2  = (const float*)d_in[15];

    float* out = (float*)d_out;
    float* z_out = out;
    float* adj_out = out + (size_t)NN * ZC;

    void* p;
    cudaGetSymbolAddress(&p, g_lin0); float* lin0 = (float*)p;
    cudaGetSymbolAddress(&p, g_gat0); float* gat0 = (float*)p;
    cudaGetSymbolAddress(&p, g_lin1); float* lin1 = (float*)p;
    cudaGetSymbolAddress(&p, g_lin2); float* lin2 = (float*)p;
    cudaGetSymbolAddress(&p, g_mean); float* meanp = (float*)p;
    cudaGetSymbolAddress(&p, g_lstd); float* lstdp = (float*)p;
    cudaGetSymbolAddress(&p, g_el);  float* el = (float*)p;
    cudaGetSymbolAddress(&p, g_er);  float* er = (float*)p;
    cudaGetSymbolAddress(&p, g_el2); float* el2 = (float*)p;
    cudaGetSymbolAddress(&p, g_er2); float* er2 = (float*)p;

    // edge sort by dst (shared by all 3 GAT layers)
    k_zero_deg<<<(NN + 255) / 256, 256>>>();
    k_hist<<<(NE + 255) / 256, 256>>>(dst);
    k_scan<<<1, 1024>>>();
    k_scatter<<<(NE + 255) / 256, 256>>>(src, dst);

    const int ngrid = (NN * NH + 255) / 256;

    // ---- layer 0: 512 -> 256, relu ----
    k_sgemm<<<dim3(HIDC / 64, (NN + 63) / 64), 256>>>(features, W0, lin0, NN, FIN, HIDC);
    k_elr<ND0><<<ngrid, 256>>>(lin0, al0, ar0, el, er);
    k_gat_fused<ND0, true><<<NN, HIDC>>>(lin0, el, er, b0, gat0);

    // ---- layers 1 & 2: 256 -> 64 ----
    k_sgemm<<<dim3(ZC / 64, (NN + 63) / 64), 256>>>(gat0, W1, lin1, NN, HIDC, ZC);
    k_sgemm<<<dim3(ZC / 64, (NN + 63) / 64), 256>>>(gat0, W2, lin2, NN, HIDC, ZC);
    k_elr<ND1><<<ngrid, 256>>>(lin1, al1, ar1, el, er);
    k_elr<ND1><<<ngrid, 256>>>(lin2, al2, ar2, el2, er2);
    k_gat_fused<ND1, false><<<NN, ZC>>>(lin1, el, er, b1, meanp);
    k_gat_fused<ND1, false><<<NN, ZC>>>(lin2, el2, er2, b2, lstdp);

    // ---- z = mean + noise * exp(log_std), split to bf16 hi/lo (padded) ----
    k_z<<<(NN * ZC + 255) / 256, 256>>>(noise, z_out);
    k_split<<<(NPAD * ZC + 255) / 256, 256>>>(z_out);

    // ---- adj = sigmoid(z @ z^T) via tcgen05, serial multi-tile ----
    cudaFuncSetAttribute(k_adj_tc3, cudaFuncAttributeMaxDynamicSharedMemorySize, TC3_SMEM);
    k_adj_tc3<<<dim3(CCH, NPAD / 128), 128, TC3_SMEM>>>(adj_out);
}

// round 10
// speedup vs baseline: 1.1950x; 1.1950x over previous
#include <cuda_runtime.h>
#include <cuda_bf16.h>
#include <cstdint>
#include <math.h>

#define NN 10000
#define NPAD 10112           // 79 * 128
#define NE 320000
#define FIN 512
#define HIDC 256
#define ZC 64
#define NH 8
#define ND0 32
#define ND1 8
#define NEG_SLOPE 0.2f

// ---------------- scratch (static device memory; no allocations) ----------------
__device__ float g_lin0[NN * HIDC];
__device__ float g_gat0[NN * HIDC];
__device__ float g_lin1[NN * ZC];
__device__ float g_lin2[NN * ZC];
__device__ float g_mean[NN * ZC];
__device__ float g_lstd[NN * ZC];
__device__ float g_el[NN * NH];
__device__ float g_er[NN * NH];
__device__ float g_el2[NN * NH];
__device__ float g_er2[NN * NH];
__device__ float g_e[NE * NH];        // per-edge scratch (sorted order)
__device__ int   g_deg[NN];
__device__ int   g_off[NN + 1];
__device__ int   g_cur[NN];
__device__ int   g_ssrc[NE];
__device__ __nv_bfloat16 g_zhi[NPAD * ZC];
__device__ __nv_bfloat16 g_zlo[NPAD * ZC];
__device__ __nv_bfloat16 g_xhi[NPAD * FIN];
__device__ __nv_bfloat16 g_xlo[NPAD * FIN];
__device__ __nv_bfloat16 g_w0thi[HIDC * FIN];
__device__ __nv_bfloat16 g_w0tlo[HIDC * FIN];

// Feature gate: tcgen05 only exists on the 'a' targets.
#if defined(__CUDA_ARCH_FEAT_SM103_ALL) || defined(__CUDA_ARCH_FEAT_SM100_ALL) || defined(__CUDA_ARCH_FEAT_SM101_ALL)
#define HAS_TCGEN05 1
#else
#define HAS_TCGEN05 0
#endif

// ---------------- PTX helpers ----------------
__device__ __forceinline__ uint32_t smem_u32(const void* p) {
    uint32_t a;
    asm("{ .reg .u64 t; cvta.to.shared.u64 t, %1; cvt.u32.u64 %0, t; }" : "=r"(a) : "l"(p));
    return a;
}
__device__ __forceinline__ uint32_t elect1() {
    uint32_t r;
    asm volatile("{ .reg .pred p; elect.sync _|p, 0xFFFFFFFF; selp.b32 %0,1,0,p; }" : "=r"(r));
    return r;
}
#define MBAR_INIT(mbar, cnt) \
    asm volatile("mbarrier.init.shared.b64 [%0], %1;" :: "r"((uint32_t)(mbar)), "r"((uint32_t)(cnt)) : "memory")
#define MBAR_INVAL(mbar) \
    asm volatile("mbarrier.inval.shared.b64 [%0];" :: "r"((uint32_t)(mbar)) : "memory")
#define MBAR_WAIT(mbar, parity) do {                                           \
    uint32_t _m = (uint32_t)(mbar), _p = (uint32_t)(parity), _d;               \
    asm volatile("{ .reg .pred p; mbarrier.try_wait.parity.acquire.cta.shared::cta.b64 p, [%1], %2; selp.b32 %0,1,0,p; }" \
                 : "=r"(_d) : "r"(_m), "r"(_p) : "memory");                    \
    if (!_d) {                                                                 \
        asm volatile("{ .reg .pred P1; WL%=: mbarrier.try_wait.parity.acquire.cta.shared::cta.b64 P1, [%0], %1, 0x989680; @P1 bra.uni WD%=; bra.uni WL%=; WD%=: }" \
                     :: "r"(_m), "r"(_p) : "memory");                          \
    }                                                                          \
} while (0)
#define FENCE_PROXY_ASYNC() asm volatile("fence.proxy.async.shared::cta;" ::: "memory")

#if HAS_TCGEN05
#define TC_ALLOC(saddr, n) \
    asm volatile("tcgen05.alloc.cta_group::1.sync.aligned.shared::cta.b32 [%0], %1;" \
                 :: "r"((uint32_t)(saddr)), "r"((uint32_t)(n)) : "memory")
#define TC_RELINQ() \
    asm volatile("tcgen05.relinquish_alloc_permit.cta_group::1.sync.aligned;")
#define TC_DEALLOC(tmem, n) \
    asm volatile("tcgen05.dealloc.cta_group::1.sync.aligned.b32 %0, %1;" :: "r"(tmem), "r"((uint32_t)(n)))
#define TC_COMMIT(mbar) \
    asm volatile("tcgen05.commit.cta_group::1.mbarrier::arrive::one.shared::cluster.b64 [%0];" \
                 :: "r"((uint32_t)(mbar)) : "memory")
#define TC_FENCE_AFTER() asm volatile("tcgen05.fence::after_thread_sync;" ::: "memory")
#define TC_FENCE_BEFORE() asm volatile("tcgen05.fence::before_thread_sync;" ::: "memory")
#define TC_WAIT_LD() asm volatile("tcgen05.wait::ld.sync.aligned;" ::: "memory")
#define TC_LD_X32(r, tmem_addr) \
    asm volatile( \
        "tcgen05.ld.sync.aligned.32x32b.x32.b32 " \
        "{%0, %1, %2, %3, %4, %5, %6, %7, " \
        " %8, %9, %10, %11, %12, %13, %14, %15, " \
        " %16, %17, %18, %19, %20, %21, %22, %23, " \
        " %24, %25, %26, %27, %28, %29, %30, %31}, [%32];" \
        : "=r"((r)[0]),  "=r"((r)[1]),  "=r"((r)[2]),  "=r"((r)[3]), \
          "=r"((r)[4]),  "=r"((r)[5]),  "=r"((r)[6]),  "=r"((r)[7]), \
          "=r"((r)[8]),  "=r"((r)[9]),  "=r"((r)[10]), "=r"((r)[11]), \
          "=r"((r)[12]), "=r"((r)[13]), "=r"((r)[14]), "=r"((r)[15]), \
          "=r"((r)[16]), "=r"((r)[17]), "=r"((r)[18]), "=r"((r)[19]), \
          "=r"((r)[20]), "=r"((r)[21]), "=r"((r)[22]), "=r"((r)[23]), \
          "=r"((r)[24]), "=r"((r)[25]), "=r"((r)[26]), "=r"((r)[27]), \
          "=r"((r)[28]), "=r"((r)[29]), "=r"((r)[30]), "=r"((r)[31]) \
        : "r"(tmem_addr))

__device__ __forceinline__ void mma_f16_ss(uint32_t d, uint64_t a, uint64_t b,
                                           uint32_t idesc, bool accum) {
    uint32_t en = accum ? 1u : 0u;
    asm volatile(
        "{\n\t"
        ".reg .pred p;\n\t"
        "setp.ne.u32 p, %5, 0;\n\t"
        "tcgen05.mma.cta_group::1.kind::f16 [%0], %1, %2, %3, {%4, %4, %4, %4}, p;\n\t"
        "}"
        :: "r"(d), "l"(a), "l"(b), "r"(idesc), "r"(0u), "r"(en)
        : "memory");
}
#endif  // HAS_TCGEN05

// SW128 SMEM descriptor (version=1, SBO=64, LBO=1)
__device__ __forceinline__ uint64_t mk_desc(uint32_t saddr) {
    const uint64_t BASE =
        (uint64_t(2) << 61) | (uint64_t(1) << 46) | (uint64_t(64) << 32) | (uint64_t(1) << 16);
    return BASE | ((uint64_t)(saddr >> 4) & 0x3FFF);
}
__device__ __forceinline__ uint32_t swz128(uint32_t off) {
    return off ^ ((off >> 3) & 0x70);
}

// ---------------- counting sort of edges by dst ----------------
__global__ void k_zero_deg() {
    int i = blockIdx.x * blockDim.x + threadIdx.x;
    if (i < NN) g_deg[i] = 0;
}

__global__ void k_hist(const int* __restrict__ dst) {
    int i = blockIdx.x * blockDim.x + threadIdx.x;
    if (i < NE) atomicAdd(&g_deg[dst[i]], 1);
}

__global__ void k_scan() {
    const int CH = 10;
    __shared__ int sh[1024];
    int t = threadIdx.x;
    int base = t * CH;
    int vals[CH];
    int loc = 0;
#pragma unroll
    for (int i = 0; i < CH; i++) {
        int idx = base + i;
        vals[i] = (idx < NN) ? g_deg[idx] : 0;
        loc += vals[i];
    }
    sh[t] = loc;
    __syncthreads();
    for (int off = 1; off < 1024; off <<= 1) {
        int v = (t >= off) ? sh[t - off] : 0;
        __syncthreads();
        sh[t] += v;
        __syncthreads();
    }
    int run = sh[t] - loc;
#pragma unroll
    for (int i = 0; i < CH; i++) {
        int idx = base + i;
        if (idx < NN) {
            g_off[idx] = run;
            g_cur[idx] = run;
            run += vals[i];
        }
    }
    if (t == 0) g_off[NN] = NE;
}

__global__ void k_scatter(const int* __restrict__ src, const int* __restrict__ dst) {
    int e = blockIdx.x * blockDim.x + threadIdx.x;
    if (e < NE) {
        int d = dst[e];
        int pos = atomicAdd(&g_cur[d], 1);
        g_ssrc[pos] = src[e];
    }
}

// ---------------- fp32 tiled GEMM (layers 1/2 only) ----------------
__global__ __launch_bounds__(256) void k_sgemm(const float* __restrict__ A,
                                               const float* __restrict__ B,
                                               float* __restrict__ C,
                                               int M, int K, int Nn) {
    __shared__ float As[64 * 32];
    __shared__ float Bs[32 * 64];
    int tid = threadIdx.x;
    int tx = tid & 15, ty = tid >> 4;
    int rowBase = blockIdx.y * 64;
    int colBase = blockIdx.x * 64;
    float acc[4][4] = {};

    for (int kb = 0; kb < K; kb += 32) {
        {
            int r = tid >> 3;
            int c = (tid & 7) << 2;
#pragma unroll
            for (int p = 0; p < 2; p++) {
                int rr = r + p * 32;
                int grow = rowBase + rr;
                float4 v = make_float4(0.f, 0.f, 0.f, 0.f);
                if (grow < M) v = *(const float4*)(A + (size_t)grow * K + kb + c);
                *(float4*)(As + rr * 32 + c) = v;
            }
            int r2 = tid >> 4;
            int c2 = (tid & 15) << 2;
#pragma unroll
            for (int p = 0; p < 2; p++) {
                int rr = r2 + p * 16;
                float4 v = *(const float4*)(B + (size_t)(kb + rr) * Nn + colBase + c2);
                *(float4*)(Bs + rr * 64 + c2) = v;
            }
        }
        __syncthreads();
#pragma unroll
        for (int kk = 0; kk < 32; kk++) {
            float4 b0 = *(const float4*)(Bs + kk * 64 + tx * 4);
            float a0 = As[(ty * 4 + 0) * 32 + kk];
            float a1 = As[(ty * 4 + 1) * 32 + kk];
            float a2 = As[(ty * 4 + 2) * 32 + kk];
            float a3 = As[(ty * 4 + 3) * 32 + kk];
            acc[0][0] += a0 * b0.x; acc[0][1] += a0 * b0.y; acc[0][2] += a0 * b0.z; acc[0][3] += a0 * b0.w;
            acc[1][0] += a1 * b0.x; acc[1][1] += a1 * b0.y; acc[1][2] += a1 * b0.z; acc[1][3] += a1 * b0.w;
            acc[2][0] += a2 * b0.x; acc[2][1] += a2 * b0.y; acc[2][2] += a2 * b0.z; acc[2][3] += a2 * b0.w;
            acc[3][0] += a3 * b0.x; acc[3][1] += a3 * b0.y; acc[3][2] += a3 * b0.z; acc[3][3] += a3 * b0.w;
        }
        __syncthreads();
    }
#pragma unroll
    for (int i = 0; i < 4; i++) {
        int grow = rowBase + ty * 4 + i;
        if (grow < M) {
            *(float4*)(C + (size_t)grow * Nn + colBase + tx * 4) =
                make_float4(acc[i][0], acc[i][1], acc[i][2], acc[i][3]);
        }
    }
}

// ---------------- feature / W0^T bf16 hi-lo splits ----------------
__global__ void k_splitx(const float* __restrict__ x) {
    int i = blockIdx.x * blockDim.x + threadIdx.x;
    if (i >= NPAD * FIN) return;
    int row = i / FIN;
    float v = (row < NN) ? x[(size_t)row * FIN + (i % FIN)] : 0.f;
    __nv_bfloat16 h = __float2bfloat16(v);
    g_xhi[i] = h;
    g_xlo[i] = __float2bfloat16(v - __bfloat162float(h));
}

__global__ void k_w0t(const float* __restrict__ W0) {
    int i = blockIdx.x * blockDim.x + threadIdx.x;
    if (i >= HIDC * FIN) return;
    int n = i / FIN, k = i % FIN;
    float v = W0[(size_t)k * HIDC + n];
    __nv_bfloat16 h = __float2bfloat16(v);
    g_w0thi[i] = h;
    g_w0tlo[i] = __float2bfloat16(v - __bfloat162float(h));
}

// ---------------- lin0 = X @ W0 via tcgen05 (bf16 hi/lo, 3 passes) ----------------
// Grid 79, block 128. Per CTA: 128 rows x 256 cols, K=512 in 8x64 chunks,
// two N=128 TMEM accumulators, per-chunk commit/wait before buffer reuse.
#define TC_IDESC 0x8200490u
#define L_AH 1024
#define L_AL (1024 + 16384)
#define L_BH (1024 + 2 * 16384)
#define L_BL (1024 + 4 * 16384)
#define L_SMEM (1024 + 6 * 16384)

__global__ __launch_bounds__(128)
void k_lin0_tc(float* __restrict__ out) {
#if HAS_TCGEN05
    extern __shared__ char smem[];
    uint32_t sb = smem_u32(smem);
    int tid = threadIdx.x, wid = tid >> 5, lid = tid & 31;
    int row0 = blockIdx.x * 128;

    if (wid == 0) {
        TC_ALLOC(sb + 0, 256);
        TC_RELINQ();
    }
    if (tid == 0) MBAR_INIT(sb + 8, 1);
    __syncthreads();

    uint32_t tmem;
    asm volatile("ld.shared.b32 %0, [%1];" : "=r"(tmem) : "r"(sb + 0));
    uint64_t dAh = mk_desc(sb + L_AH);
    uint64_t dAl = mk_desc(sb + L_AL);
    int ph = 0;

    for (int kb = 0; kb < 8; kb++) {
        int k0 = kb * 64;
        // A hi/lo chunk: 128 rows x 64 bf16 (128B rows, SW128)
#pragma unroll
        for (int it = 0; it < 8; it++) {
            int idx = it * 128 + tid;
            int r = idx >> 3;
            int c = idx & 7;
            uint32_t sw = swz128((uint32_t)(r * 128 + c * 16));
            *(uint4*)(smem + L_AH + sw) =
                *((const uint4*)(g_xhi + (size_t)(row0 + r) * FIN + k0) + c);
            *(uint4*)(smem + L_AL + sw) =
                *((const uint4*)(g_xlo + (size_t)(row0 + r) * FIN + k0) + c);
        }
        // B hi/lo chunk: 2 col-tiles x 128 rows x 64 bf16
#pragma unroll
        for (int it = 0; it < 16; it++) {
            int idx = it * 128 + tid;          // 0..2047
            int j = idx >> 10;
            int rem = idx & 1023;
            int rr = rem >> 3;
            int c = rem & 7;
            uint32_t sw = swz128((uint32_t)(rr * 128 + c * 16)) + j * 16384;
            *(uint4*)(smem + L_BH + sw) =
                *((const uint4*)(g_w0thi + (size_t)(j * 128 + rr) * FIN + k0) + c);
            *(uint4*)(smem + L_BL + sw) =
                *((const uint4*)(g_w0tlo + (size_t)(j * 128 + rr) * FIN + k0) + c);
        }
        FENCE_PROXY_ASYNC();
        __syncthreads();

        if (wid == 0 && elect1()) {
#pragma unroll
            for (int j = 0; j < 2; j++) {
                uint64_t dBh = mk_desc(sb + L_BH + j * 16384);
                uint64_t dBl = mk_desc(sb + L_BL + j * 16384);
                uint32_t dacc = tmem + j * 128;
#pragma unroll
                for (int p = 0; p < 3; p++) {
                    uint64_t da = (p == 2) ? dAl : dAh;
                    uint64_t db = (p == 1) ? dBl : dBh;
#pragma unroll
                    for (int k = 0; k < 4; k++) {
                        bool first = (kb == 0) && (p == 0) && (k == 0);
                        mma_f16_ss(dacc, da + k * 2, db + k * 2, TC_IDESC, !first);
                    }
                }
            }
            TC_COMMIT(sb + 8);
        }
        MBAR_WAIT(sb + 8, ph & 1);
        ph++;
        __syncthreads();   // MMAs done: safe to overwrite smem next chunk
    }

    TC_FENCE_AFTER();
    int r = row0 + wid * 32 + lid;
#pragma unroll
    for (int j = 0; j < 2; j++) {
#pragma unroll
        for (int ch = 0; ch < 4; ch++) {
            uint32_t dr[32];
            TC_LD_X32(dr, tmem + j * 128 + ch * 32);
            TC_WAIT_LD();
            if (r < NN) {
                float* orow = out + (size_t)r * HIDC + j * 128 + ch * 32;
#pragma unroll
                for (int q = 0; q < 8; q++)
                    *(float4*)(orow + q * 4) = make_float4(
                        __uint_as_float(dr[q * 4]), __uint_as_float(dr[q * 4 + 1]),
                        __uint_as_float(dr[q * 4 + 2]), __uint_as_float(dr[q * 4 + 3]));
            }
        }
    }
    TC_FENCE_BEFORE();
    __syncthreads();
    if (tid == 0) MBAR_INVAL(sb + 8);
    __syncthreads();
    if (wid == 0) TC_DEALLOC(tmem, 256);
#endif  // HAS_TCGEN05
}

// ---------------- el/er ----------------
template <int D>
__global__ void k_elr(const float* __restrict__ lin,
                      const float* __restrict__ al,
                      const float* __restrict__ ar,
                      float* __restrict__ elo, float* __restrict__ ero) {
    int i = blockIdx.x * blockDim.x + threadIdx.x;
    if (i >= NN * NH) return;
    int n = i / NH, h = i % NH;
    float el = 0.f, er = 0.f;
#pragma unroll
    for (int d = 0; d < D; d++) {
        float v = lin[n * (NH * D) + h * D + d];
        el += v * al[h * D + d];
        er += v * ar[h * D + d];
    }
    elo[i] = el;
    ero[i] = er;
}

// ---------------- fused per-node GAT ----------------
template <int D, bool RELU>
__global__ void k_gat_fused(const float* __restrict__ lin,
                            const float* __restrict__ elp,
                            const float* __restrict__ erp,
                            const float* __restrict__ bias,
                            float* __restrict__ out) {
    const int C = NH * D;
    int n = blockIdx.x;
    int tid = threadIdx.x;
    int beg = g_off[n], end = g_off[n + 1];
    __shared__ int   s_m[NH];
    __shared__ float s_sum[NH];
    __shared__ int   s_src[32];
    __shared__ float s_ex[32 * NH];
    if (tid < NH) { s_m[tid] = __float_as_int(-INFINITY); s_sum[tid] = 0.f; }
    __syncthreads();

    {
        int h = tid & 7;
        float ern = erp[n * NH + h];
        for (int j0 = beg + (tid >> 3); j0 < end; j0 += C / NH) {
            int s = g_ssrc[j0];
            float v = elp[s * NH + h] + ern;
            v = (v > 0.f) ? v : NEG_SLOPE * v;
            g_e[(size_t)j0 * NH + h] = v;
            if (v >= 0.f)
                atomicMax(&s_m[h], __float_as_int(v));
            else
                atomicMin((unsigned int*)&s_m[h], (unsigned int)__float_as_int(v));
        }
    }
    __syncthreads();

    float acc = 0.f;
    int hA = tid / D;
    for (int base = beg; base < end; base += 32) {
        int cnt = min(32, end - base);
        __syncthreads();
        if (tid < cnt) s_src[tid] = g_ssrc[base + tid];
        for (int i = tid; i < cnt * NH; i += C) {
            float ex = __expf(g_e[(size_t)base * NH + i] - __int_as_float(s_m[i & 7]));
            s_ex[i] = ex;
            atomicAdd(&s_sum[i & 7], ex);
        }
        __syncthreads();
        for (int jj = 0; jj < cnt; jj++)
            acc += lin[(size_t)s_src[jj] * C + tid] * s_ex[jj * NH + hA];
    }
    float v = (end > beg) ? acc / s_sum[hA] : 0.f;
    v += bias[tid];
    if (RELU) v = fmaxf(v, 0.f);
    out[(size_t)n * C + tid] = v;
}

// ---------------- z = mean + noise * exp(log_std), then bf16 hi/lo split ----------------
__global__ void k_z(const float* __restrict__ noise, float* __restrict__ zout) {
    int i = blockIdx.x * blockDim.x + threadIdx.x;
    if (i < NN * ZC) zout[i] = g_mean[i] + noise[i] * expf(g_lstd[i]);
}

__global__ void k_split(const float* __restrict__ z) {
    int i = blockIdx.x * blockDim.x + threadIdx.x;
    if (i >= NPAD * ZC) return;
    if (i < NN * ZC) {
        float v = z[i];
        __nv_bfloat16 h = __float2bfloat16(v);
        g_zhi[i] = h;
        g_zlo[i] = __float2bfloat16(v - __bfloat162float(h));
    } else {
        g_zhi[i] = __float2bfloat16(0.f);
        g_zlo[i] = __float2bfloat16(0.f);
    }
}

// ---------------- adj = sigmoid(z @ z^T) via tcgen05 (round-7 proven) ----------------
#define TSM_AH 1024
#define TSM_AL (1024 + 16384)
#define TSM_BH (1024 + 2 * 16384)
#define TSM_BL (1024 + 3 * 16384)
#define TC_SMEM (1024 + 4 * 16384)

__global__ __launch_bounds__(128)
void k_adj_tc(float* __restrict__ adj) {
#if HAS_TCGEN05
    extern __shared__ char smem[];
    uint32_t sb = smem_u32(smem);
    int tid = threadIdx.x, wid = tid >> 5, lid = tid & 31;
    int row0 = blockIdx.y * 128, col0 = blockIdx.x * 128;

    if (wid == 0) {
        TC_ALLOC(sb + 0, 128);
        TC_RELINQ();
    }
    if (tid == 0) MBAR_INIT(sb + 8, 1);

#pragma unroll
    for (int it = 0; it < 8; it++) {
        int idx = it * 128 + tid;
        int r = idx >> 3;
        int c = idx & 7;
        uint32_t sw = swz128((uint32_t)(r * 128 + c * 16));
        const uint4* pAh = (const uint4*)(g_zhi + (size_t)(row0 + r) * ZC) + c;
        const uint4* pAl = (const uint4*)(g_zlo + (size_t)(row0 + r) * ZC) + c;
        const uint4* pBh = (const uint4*)(g_zhi + (size_t)(col0 + r) * ZC) + c;
        const uint4* pBl = (const uint4*)(g_zlo + (size_t)(col0 + r) * ZC) + c;
        *(uint4*)(smem + TSM_AH + sw) = *pAh;
        *(uint4*)(smem + TSM_AL + sw) = *pAl;
        *(uint4*)(smem + TSM_BH + sw) = *pBh;
        *(uint4*)(smem + TSM_BL + sw) = *pBl;
    }
    __syncthreads();

    uint32_t tmem;
    asm volatile("ld.shared.b32 %0, [%1];" : "=r"(tmem) : "r"(sb + 0));

    if (wid == 0 && elect1()) {
        uint64_t dAh = mk_desc(sb + TSM_AH);
        uint64_t dAl = mk_desc(sb + TSM_AL);
        uint64_t dBh = mk_desc(sb + TSM_BH);
        uint64_t dBl = mk_desc(sb + TSM_BL);
        bool first = true;
#pragma unroll
        for (int p = 0; p < 3; p++) {
            uint64_t da = (p == 2) ? dAl : dAh;
            uint64_t db = (p == 1) ? dBl : dBh;
#pragma unroll
            for (int k = 0; k < 4; k++) {
                mma_f16_ss(tmem, da + k * 2, db + k * 2, TC_IDESC, !first);
                first = false;
            }
        }
        TC_COMMIT(sb + 8);
    }

    MBAR_WAIT(sb + 8, 0);
    TC_FENCE_AFTER();

    int r = row0 + wid * 32 + lid;
#pragma unroll
    for (int ch = 0; ch < 4; ch++) {
        uint32_t dr[32];
        TC_LD_X32(dr, tmem + ch * 32);
        TC_WAIT_LD();
        if (r < NN) {
            int cbase = col0 + ch * 32;
            float v[32];
#pragma unroll
            for (int j = 0; j < 32; j++)
                v[j] = 1.f / (1.f + __expf(-__uint_as_float(dr[j])));
            float* orow = adj + (size_t)r * NN + cbase;
            if (cbase + 31 < NN) {
#pragma unroll
                for (int q = 0; q < 8; q++)
                    *(float4*)(orow + q * 4) =
                        make_float4(v[q * 4], v[q * 4 + 1], v[q * 4 + 2], v[q * 4 + 3]);
            } else {
#pragma unroll
                for (int j = 0; j < 32; j++)
                    if (cbase + j < NN) orow[j] = v[j];
            }
        }
    }
    TC_FENCE_BEFORE();
    __syncthreads();
    if (tid == 0) MBAR_INVAL(sb + 8);
    __syncthreads();
    if (wid == 0) TC_DEALLOC(tmem, 128);
#endif  // HAS_TCGEN05
}

// ---------------- launcher ----------------
extern "C" void kernel_launch(void* const* d_in, const int* in_sizes, int n_in,
                              void* d_out, int out_size) {
    const float* features = (const float*)d_in[0];
    const int*   src      = (const int*)d_in[1];
    const int*   dst      = (const int*)d_in[2];
    const float* noise    = (const float*)d_in[3];
    const float* W0  = (const float*)d_in[4];
    const float* al0 = (const float*)d_in[5];
    const float* ar0 = (const float*)d_in[6];
    const float* b0  = (const float*)d_in[7];
    const float* W1  = (const float*)d_in[8];
    const float* al1 = (const float*)d_in[9];
    const float* ar1 = (const float*)d_in[10];
    const float* b1  = (const float*)d_in[11];
    const float* W2  = (const float*)d_in[12];
    const float* al2 = (const float*)d_in[13];
    const float* ar2 = (const float*)d_in[14];
    const float* b2  = (const float*)d_in[15];

    float* out = (float*)d_out;
    float* z_out = out;
    float* adj_out = out + (size_t)NN * ZC;

    void* p;
    cudaGetSymbolAddress(&p, g_lin0); float* lin0 = (float*)p;
    cudaGetSymbolAddress(&p, g_gat0); float* gat0 = (float*)p;
    cudaGetSymbolAddress(&p, g_lin1); float* lin1 = (float*)p;
    cudaGetSymbolAddress(&p, g_lin2); float* lin2 = (float*)p;
    cudaGetSymbolAddress(&p, g_mean); float* meanp = (float*)p;
    cudaGetSymbolAddress(&p, g_lstd); float* lstdp = (float*)p;
    cudaGetSymbolAddress(&p, g_el);  float* el = (float*)p;
    cudaGetSymbolAddress(&p, g_er);  float* er = (float*)p;
    cudaGetSymbolAddress(&p, g_el2); float* el2 = (float*)p;
    cudaGetSymbolAddress(&p, g_er2); float* er2 = (float*)p;

    // edge sort by dst (shared by all 3 GAT layers)
    k_zero_deg<<<(NN + 255) / 256, 256>>>();
    k_hist<<<(NE + 255) / 256, 256>>>(dst);
    k_scan<<<1, 1024>>>();
    k_scatter<<<(NE + 255) / 256, 256>>>(src, dst);

    const int ngrid = (NN * NH + 255) / 256;

    // ---- layer 0: 512 -> 256, relu (tcgen05 GEMM) ----
    k_splitx<<<(NPAD * FIN + 255) / 256, 256>>>(features);
    k_w0t<<<(HIDC * FIN + 255) / 256, 256>>>(W0);
    cudaFuncSetAttribute(k_lin0_tc, cudaFuncAttributeMaxDynamicSharedMemorySize, L_SMEM);
    k_lin0_tc<<<NPAD / 128, 128, L_SMEM>>>(lin0);
    k_elr<ND0><<<ngrid, 256>>>(lin0, al0, ar0, el, er);
    k_gat_fused<ND0, true><<<NN, HIDC>>>(lin0, el, er, b0, gat0);

    // ---- layers 1 & 2: 256 -> 64 ----
    k_sgemm<<<dim3(ZC / 64, (NN + 63) / 64), 256>>>(gat0, W1, lin1, NN, HIDC, ZC);
    k_sgemm<<<dim3(ZC / 64, (NN + 63) / 64), 256>>>(gat0, W2, lin2, NN, HIDC, ZC);
    k_elr<ND1><<<ngrid, 256>>>(lin1, al1, ar1, el, er);
    k_elr<ND1><<<ngrid, 256>>>(lin2, al2, ar2, el2, er2);
    k_gat_fused<ND1, false><<<NN, ZC>>>(lin1, el, er, b1, meanp);
    k_gat_fused<ND1, false><<<NN, ZC>>>(lin2, el2, er2, b2, lstdp);

    // ---- z = mean + noise * exp(log_std), split to bf16 hi/lo (padded) ----
    k_z<<<(NN * ZC + 255) / 256, 256>>>(noise, z_out);
    k_split<<<(NPAD * ZC + 255) / 256, 256>>>(z_out);

    // ---- adj = sigmoid(z @ z^T) via tcgen05 (round-7 config) ----
    cudaFuncSetAttribute(k_adj_tc, cudaFuncAttributeMaxDynamicSharedMemorySize, TC_SMEM);
    k_adj_tc<<<dim3(NPAD / 128, NPAD / 128), 128, TC_SMEM>>>(adj_out);
}